// round 6
// baseline (speedup 1.0000x reference)
#include <cuda_runtime.h>
#include <cuda_bf16.h>

// CausalSequenceCML: 16 fused steps of depthwise-causal-conv logistic CML.
// B=4, T=4096, C=512, K=4, STEPS=16.
//
// Round-6: R5 warp-per-channel structure, tuned at the FFMA rt=2 cap:
//  - LL=20 cells/lane, NTILES=7 (7x640=4480 tile-cells vs 8x576=4608): -3% FFMA.
//  - Software-pipelined shfl: head/tail m' computed first, shfls issued,
//    17 interior cells (85 FMAs) hide the 26-cyc SHFL latency, then the
//    3 head cells consume the shfl results. No per-step serial stall.
//  - launch_bounds(256,4): 4 CTAs/SM (50% occ).
// No smem / no barriers in the 16-step hot loop.

#define Bdim 4
#define Tdim 4096
#define Cdim 512
#define NSTEPS 16
#define WC 8                  // channels (warps) per block
#define LL 20                 // cells per lane
#define TILE (32 * LL)        // 640
#define HALO 48               // 3 * NSTEPS
#define VALID (TILE - HALO)   // 592
#define NTILES 7              // 7*592 = 4144 >= 4096
#define ROWP (TILE + 1)       // smem row pad

__global__ void __launch_bounds__(32 * WC, 4)
cml_kernel(const float* __restrict__ drive,
           const float* __restrict__ r,
           const float* __restrict__ eps,
           const float* __restrict__ beta,
           const float* __restrict__ Kc,
           float* __restrict__ out)
{
    __shared__ float st[WC][ROWP];     // staging: [channel][time]

    const int tid  = threadIdx.x;
    const int lane = tid & 31;
    const int w    = tid >> 5;               // warp = channel within block
    const int c0   = blockIdx.y * WC;
    const int cg   = c0 + w;
    const int b    = blockIdx.z;
    const int gt0  = (int)blockIdx.x * VALID - HALO;
    const int base = b * (Tdim * Cdim);

    // ---- stage: global -> smem [c][t] (32B-sector coalesced) ----
#pragma unroll
    for (int it = 0; it < TILE * WC / (32 * WC); it++) {
        const int idx = it * (32 * WC) + tid;
        const int t = idx >> 3;
        const int c = idx & 7;
        const int gt = gt0 + t;
        float d = 0.0f;
        if (gt >= 0 && gt < Tdim)
            d = drive[base + gt * Cdim + c0 + c];
        st[c][t] = d;
    }

    // per-channel (warp-uniform) constants; fold r into conv weights
    const float rr = r[cg];
    const float ee = eps[cg];
    const float bb = beta[cg];
    const float k0 = Kc[cg * 4 + 0];
    const float k1 = Kc[cg * 4 + 1];
    const float k2 = Kc[cg * 4 + 2];
    const float k3 = Kc[cg * 4 + 3];
    const float onemb = 1.0f - bb;
    const float A  = onemb * (1.0f - ee);
    const float Bc = onemb * ee;
    const float v3 = fmaf(Bc, k3, A) * rr;   // coeff of m'[t]
    const float v2 = Bc * k2 * rr;           // m'[t-1]
    const float v1 = Bc * k1 * rr;           // m'[t-2]
    const float v0 = Bc * k0 * rr;           // m'[t-3]

    __syncthreads();

    // ---- smem -> registers (lane-major time) ----
    float g[LL], D[LL];
#pragma unroll
    for (int i = 0; i < LL; i++) {
        const float d = st[w][lane * LL + i];
        g[i] = d;
        D[i] = bb * d;
    }

    // ---- 16 fused steps; warp-synchronous halo via pipelined shfl ----
#pragma unroll 1
    for (int step = 0; step < NSTEPS; step++) {
        // m' of head cells (old g) and tail cells
        const float h0 = fmaf(-g[0], g[0], g[0]);
        const float h1 = fmaf(-g[1], g[1], g[1]);
        const float h2 = fmaf(-g[2], g[2], g[2]);
        const float tA = fmaf(-g[LL-3], g[LL-3], g[LL-3]);
        const float tB = fmaf(-g[LL-2], g[LL-2], g[LL-2]);
        const float tC = fmaf(-g[LL-1], g[LL-1], g[LL-1]);
        // issue shfls early; latency hidden by the interior sweep below
        float s1 = __shfl_up_sync(0xffffffffu, tC, 1);
        float s2 = __shfl_up_sync(0xffffffffu, tB, 1);
        float s3 = __shfl_up_sync(0xffffffffu, tA, 1);
        s1 = lane ? s1 : 0.0f;
        s2 = lane ? s2 : 0.0f;
        s3 = lane ? s3 : 0.0f;

        // interior sweep i = 3 .. LL-1 (uses only local m')
        float m3 = h0, m2 = h1, m1 = h2;
#pragma unroll
        for (int i = 3; i < LL; i++) {
            const float gi = g[i];
            const float m0 = (i < LL - 3) ? fmaf(-gi, gi, gi)
                           : (i == LL - 3 ? tA : (i == LL - 2 ? tB : tC));
            float acc = fmaf(v3, m0, D[i]);
            acc = fmaf(v2, m1, acc);
            acc = fmaf(v1, m2, acc);
            g[i] = fmaf(v0, m3, acc);
            m3 = m2; m2 = m1; m1 = m0;
        }

        // head cells consume shfl results
        {
            float acc = fmaf(v3, h0, D[0]);
            acc = fmaf(v2, s1, acc);
            acc = fmaf(v1, s2, acc);
            g[0] = fmaf(v0, s3, acc);
        }
        {
            float acc = fmaf(v3, h1, D[1]);
            acc = fmaf(v2, h0, acc);
            acc = fmaf(v1, s1, acc);
            g[1] = fmaf(v0, s2, acc);
        }
        {
            float acc = fmaf(v3, h2, D[2]);
            acc = fmaf(v2, h1, acc);
            acc = fmaf(v1, h0, acc);
            g[2] = fmaf(v0, s1, acc);
        }
    }

    // ---- registers -> smem (clipped) ----
    __syncthreads();
#pragma unroll
    for (int i = 0; i < LL; i++)
        st[w][lane * LL + i] = fminf(fmaxf(g[i], 1.0e-4f), 1.0f - 1.0e-4f);
    __syncthreads();

    // ---- smem -> global, skip halo ----
#pragma unroll
    for (int it = 0; it < TILE * WC / (32 * WC); it++) {
        const int idx = it * (32 * WC) + tid;
        const int t = idx >> 3;
        const int c = idx & 7;
        const int gt = gt0 + t;
        if (t >= HALO && gt < Tdim)
            out[base + gt * Cdim + c0 + c] = st[c][t];
    }
}

extern "C" void kernel_launch(void* const* d_in, const int* in_sizes, int n_in,
                              void* d_out, int out_size)
{
    const float* drive = (const float*)d_in[0];
    const float* r     = (const float*)d_in[1];
    const float* eps   = (const float*)d_in[2];
    const float* beta  = (const float*)d_in[3];
    const float* Kc    = (const float*)d_in[4];
    float* out = (float*)d_out;

    dim3 grid(NTILES, Cdim / WC, Bdim);   // 7 x 64 x 4 = 1792 CTAs
    cml_kernel<<<grid, 32 * WC>>>(drive, r, eps, beta, Kc, out);
}